// round 1
// baseline (speedup 1.0000x reference)
#include <cuda_runtime.h>

#define EDGES   65536
#define NODESN  2048
#define DI      64
#define DOUT    64
#define EPSV    1e-6f

// scratch (no cudaMalloc allowed)
__device__ float g_sidx[EDGES];   // accumulated src index per edge (exact int in float)
__device__ float g_tidx[EDGES];   // accumulated tgt index per edge
__device__ float g_a[EDGES];      // attention logit
__device__ float g_aexp[EDGES];   // exp(a - mean)
__device__ float g_asum[NODESN];  // per-target-node denominator
__device__ float g_atot;          // sum of logits (for mean)

// ---------------------------------------------------------------------------
// K0: zero all scratch + output
// ---------------------------------------------------------------------------
__global__ void k_zero(float* __restrict__ out) {
    int i = blockIdx.x * blockDim.x + threadIdx.x;
    if (i < NODESN * DOUT) out[i] = 0.0f;
    if (i < EDGES) { g_sidx[i] = 0.0f; g_tidx[i] = 0.0f; }
    if (i < NODESN) g_asum[i] = 0.0f;
    if (i == 0) g_atot = 0.0f;
}

// ---------------------------------------------------------------------------
// K1: one-hot -> index extraction. Reads the full 1 GB (src + tgt).
// Each thread owns 4 edges (one float4 column group) and a 256-row chunk.
// idx = sum_n n * onehot[n][e]  (exact: single 1.0 entry, n < 2^11)
// grid: (E/4/256, 8) x 256 threads
// ---------------------------------------------------------------------------
__global__ void k_index(const float4* __restrict__ src4,
                        const float4* __restrict__ tgt4) {
    const int g4 = blockIdx.x * blockDim.x + threadIdx.x;   // float4 group id
    const int r0 = blockIdx.y * 256;                        // row chunk start
    const int stride4 = EDGES / 4;                          // 16384
    size_t base = (size_t)r0 * stride4 + g4;

    float s0 = 0.f, s1 = 0.f, s2 = 0.f, s3 = 0.f;
    float t0 = 0.f, t1 = 0.f, t2 = 0.f, t3 = 0.f;

#pragma unroll 8
    for (int n = 0; n < 256; ++n) {
        float fn = (float)(r0 + n);
        float4 vs = src4[base];
        float4 vt = tgt4[base];
        base += stride4;
        s0 += vs.x * fn; s1 += vs.y * fn; s2 += vs.z * fn; s3 += vs.w * fn;
        t0 += vt.x * fn; t1 += vt.y * fn; t2 += vt.z * fn; t3 += vt.w * fn;
    }
    int e0 = g4 * 4;
    atomicAdd(&g_sidx[e0 + 0], s0); atomicAdd(&g_sidx[e0 + 1], s1);
    atomicAdd(&g_sidx[e0 + 2], s2); atomicAdd(&g_sidx[e0 + 3], s3);
    atomicAdd(&g_tidx[e0 + 0], t0); atomicAdd(&g_tidx[e0 + 1], t1);
    atomicAdd(&g_tidx[e0 + 2], t2); atomicAdd(&g_tidx[e0 + 3], t3);
}

// ---------------------------------------------------------------------------
// K2: per-edge attention logit a[e] = [x[s],x[t]] . W_w + b_w; global sum for mean
// ---------------------------------------------------------------------------
__global__ void k_attn(const float* __restrict__ x,
                       const float* __restrict__ Ww,
                       const float* __restrict__ bw) {
    int e = blockIdx.x * blockDim.x + threadIdx.x;
    int s = (int)(g_sidx[e] + 0.5f);
    int t = (int)(g_tidx[e] + 0.5f);

    const float4* xs = (const float4*)(x + s * DI);
    const float4* xt = (const float4*)(x + t * DI);
    const float4* w0 = (const float4*)Ww;
    const float4* w1 = (const float4*)(Ww + DI);

    float acc = bw[0];
#pragma unroll
    for (int k = 0; k < DI / 4; ++k) {
        float4 a = xs[k], b = __ldg(&w0[k]);
        acc += a.x * b.x + a.y * b.y + a.z * b.z + a.w * b.w;
        float4 c = xt[k], d = __ldg(&w1[k]);
        acc += c.x * d.x + c.y * d.y + c.z * d.z + c.w * d.w;
    }
    g_a[e] = acc;

    // warp-reduce for the mean
    float r = acc;
#pragma unroll
    for (int off = 16; off; off >>= 1) r += __shfl_xor_sync(0xFFFFFFFFu, r, off);
    if ((threadIdx.x & 31) == 0) atomicAdd(&g_atot, r);
}

// ---------------------------------------------------------------------------
// K3: a_exp = exp(a - mean); per-target denominator via atomics
// ---------------------------------------------------------------------------
__global__ void k_softmax() {
    int e = blockIdx.x * blockDim.x + threadIdx.x;
    float mean = g_atot * (1.0f / (float)EDGES);
    float ae = expf(g_a[e] - mean);
    g_aexp[e] = ae;
    int t = (int)(g_tidx[e] + 0.5f);
    atomicAdd(&g_asum[t], ae);
}

// ---------------------------------------------------------------------------
// K4: fused Y = relu(H @ W_f + b_f), weight by edge softmax, scatter to out.
// Block = 256 threads handles 64 edges. hT[k][e] staged in smem (transposed so
// the inner loop reads conflict-free float4). Each thread: 4 edges x 4 dims
// register tile -> 16 FFMA per (1 LDS + 1 LDG-L1) pair.
// ---------------------------------------------------------------------------
#define BE 64
__global__ void __launch_bounds__(256) k_out(const float* __restrict__ x,
                                             const float* __restrict__ Wf,
                                             const float* __restrict__ bf,
                                             float* __restrict__ out) {
    __shared__ float hT[2 * DI * BE];   // hT[k*64 + e], k in [0,128)
    __shared__ float we[BE];
    __shared__ int   tg[BE];

    const int tid = threadIdx.x;
    const int e0 = blockIdx.x * BE;

    // per-edge meta
    if (tid < BE) {
        int e = e0 + tid;
        int t = (int)(g_tidx[e] + 0.5f);
        tg[tid] = t;
        we[tid] = g_aexp[e] / (g_asum[t] + EPSV);
    }

    // stage hT: thread (e = tid%64, q = tid/64) loads a 32-wide slice of x row
    {
        int e = tid & 63;
        int q = tid >> 6;                 // 0,1: src halves; 2,3: tgt halves
        int ge = e0 + e;
        int node = (q < 2) ? (int)(g_sidx[ge] + 0.5f) : (int)(g_tidx[ge] + 0.5f);
        int kbase = (q & 1) * 32;         // element offset within x row
        int krow  = (q < 2) ? 0 : DI;     // offset in concatenated h
        const float4* xr = (const float4*)(x + node * DI + kbase);
#pragma unroll
        for (int i = 0; i < 8; ++i) {
            float4 v = xr[i];
            int k = krow + kbase + i * 4;
            hT[(k + 0) * BE + e] = v.x;
            hT[(k + 1) * BE + e] = v.y;
            hT[(k + 2) * BE + e] = v.z;
            hT[(k + 3) * BE + e] = v.w;
        }
    }
    __syncthreads();

    const int eg = tid & 15;   // edges eg*4 .. eg*4+3
    const int dg = tid >> 4;   // dims  dg*4 .. dg*4+3

    float acc[4][4] = {};
    const float4* Wf4 = (const float4*)Wf;
#pragma unroll 8
    for (int k = 0; k < 2 * DI; ++k) {
        float4 hv = *(const float4*)&hT[k * BE + eg * 4];
        float4 wv = __ldg(&Wf4[(k * DOUT + dg * 4) >> 2]);
        acc[0][0] += hv.x * wv.x; acc[0][1] += hv.x * wv.y; acc[0][2] += hv.x * wv.z; acc[0][3] += hv.x * wv.w;
        acc[1][0] += hv.y * wv.x; acc[1][1] += hv.y * wv.y; acc[1][2] += hv.y * wv.z; acc[1][3] += hv.y * wv.w;
        acc[2][0] += hv.z * wv.x; acc[2][1] += hv.z * wv.y; acc[2][2] += hv.z * wv.z; acc[2][3] += hv.z * wv.w;
        acc[3][0] += hv.w * wv.x; acc[3][1] += hv.w * wv.y; acc[3][2] += hv.w * wv.z; acc[3][3] += hv.w * wv.w;
    }

    float4 bv = __ldg((const float4*)&bf[dg * 4]);
#pragma unroll
    for (int i = 0; i < 4; ++i) {
        int el = eg * 4 + i;
        float w = we[el];
        int t = tg[el];
        float* op = out + t * DOUT + dg * 4;
        float y0 = fmaxf(acc[i][0] + bv.x, 0.0f) * w;
        float y1 = fmaxf(acc[i][1] + bv.y, 0.0f) * w;
        float y2 = fmaxf(acc[i][2] + bv.z, 0.0f) * w;
        float y3 = fmaxf(acc[i][3] + bv.w, 0.0f) * w;
        atomicAdd(&op[0], y0);
        atomicAdd(&op[1], y1);
        atomicAdd(&op[2], y2);
        atomicAdd(&op[3], y3);
    }
}

// ---------------------------------------------------------------------------
extern "C" void kernel_launch(void* const* d_in, const int* in_sizes, int n_in,
                              void* d_out, int out_size) {
    const float* x   = (const float*)d_in[0];
    const float* src = (const float*)d_in[1];
    const float* tgt = (const float*)d_in[2];
    const float* Wf  = (const float*)d_in[3];
    const float* bf  = (const float*)d_in[4];
    const float* Ww  = (const float*)d_in[5];
    const float* bw  = (const float*)d_in[6];
    float* out = (float*)d_out;

    k_zero<<<(NODESN * DOUT + 255) / 256, 256>>>(out);
    k_index<<<dim3(EDGES / 4 / 256, 8), 256>>>((const float4*)src,
                                               (const float4*)tgt);
    k_attn<<<EDGES / 256, 256>>>(x, Ww, bw);
    k_softmax<<<EDGES / 256, 256>>>();
    k_out<<<EDGES / BE, 256>>>(x, Wf, bf, out);
}